// round 1
// baseline (speedup 1.0000x reference)
#include <cuda_runtime.h>
#include <cstdint>

// Problem constants (fixed by the dataset)
#define KBITS 8
#define MDIM  1024   // in_features
#define NDIM  1024   // out_features
#define TROWS 8192   // B*S = 4*2048

// Scratch for the folded weight matrix W[m][n] = sum_k binary[k][m][n]*scale[k][n]
__device__ float g_W[MDIM * NDIM];

// ---------------------------------------------------------------------------
// Stage 1: fold the K per-bit +/-1 matrices and scales into one fp32 W.
// Memory-bound: reads 8*4MB binary + tiny scale, writes 4MB.
// ---------------------------------------------------------------------------
__global__ __launch_bounds__(256)
void fold_kernel(const float* __restrict__ binary,
                 const float* __restrict__ scale) {
    int idx = (blockIdx.x * blockDim.x + threadIdx.x) * 4;  // element index in [0, M*N)
    int n = idx & (NDIM - 1);
    float4 acc = make_float4(0.f, 0.f, 0.f, 0.f);
#pragma unroll
    for (int k = 0; k < KBITS; k++) {
        float4 b = *reinterpret_cast<const float4*>(binary + (size_t)k * MDIM * NDIM + idx);
        float4 s = *reinterpret_cast<const float4*>(scale + (size_t)k * NDIM + n);
        acc.x += b.x * s.x;
        acc.y += b.y * s.y;
        acc.z += b.z * s.z;
        acc.w += b.w * s.w;
    }
    *reinterpret_cast<float4*>(g_W + idx) = acc;
}

// ---------------------------------------------------------------------------
// Stage 2: out[T,N] = x[T,M] @ W[M,N] + bias[N]
// Classic tiled SGEMM: 128x128 block tile, BK=16, 256 threads, 8x8 per thread.
// ---------------------------------------------------------------------------
#define BM 128
#define BN 128
#define BK 16

__global__ __launch_bounds__(256)
void sgemm_bias_kernel(const float* __restrict__ x,
                       const float* __restrict__ bias,
                       float* __restrict__ out) {
    __shared__ float As[BK][BM + 4];  // +4 pad: keeps float4 reads 16B-aligned, cuts store conflicts
    __shared__ float Bs[BK][BN];

    const int bx = blockIdx.x;  // N tile index
    const int by = blockIdx.y;  // T tile index
    const int tid = threadIdx.x;
    const int tx = tid & 15;    // 0..15  -> 8 output cols each
    const int ty = tid >> 4;    // 0..15  -> 8 output rows each

    const float* xblk = x + (size_t)by * BM * MDIM;
    const float* wblk = g_W + (size_t)bx * BN;

    // A-load mapping: 128 rows x 16 k, float4 along k
    const int a_row = tid >> 2;        // 0..63
    const int a_col = (tid & 3) * 4;   // 0,4,8,12
    // B-load mapping: 16 k-rows x 128 n, float4 along n
    const int b_row = tid >> 5;        // 0..7
    const int b_col = (tid & 31) * 4;  // 0..124

    float acc[8][8];
#pragma unroll
    for (int i = 0; i < 8; i++)
#pragma unroll
        for (int j = 0; j < 8; j++)
            acc[i][j] = 0.f;

    for (int k0 = 0; k0 < MDIM; k0 += BK) {
        // Load A tile (x) into smem, transposed to As[k][m]
#pragma unroll
        for (int i = 0; i < 2; i++) {
            int r = a_row + i * 64;
            float4 v = *reinterpret_cast<const float4*>(xblk + (size_t)r * MDIM + k0 + a_col);
            As[a_col + 0][r] = v.x;
            As[a_col + 1][r] = v.y;
            As[a_col + 2][r] = v.z;
            As[a_col + 3][r] = v.w;
        }
        // Load B tile (W) into smem directly
#pragma unroll
        for (int i = 0; i < 2; i++) {
            int r = b_row + i * 8;
            *reinterpret_cast<float4*>(&Bs[r][b_col]) =
                *reinterpret_cast<const float4*>(wblk + (size_t)(k0 + r) * NDIM + b_col);
        }
        __syncthreads();

#pragma unroll
        for (int k = 0; k < BK; k++) {
            float a[8], b[8];
            *reinterpret_cast<float4*>(a)     = *reinterpret_cast<const float4*>(&As[k][ty * 8]);
            *reinterpret_cast<float4*>(a + 4) = *reinterpret_cast<const float4*>(&As[k][ty * 8 + 4]);
            *reinterpret_cast<float4*>(b)     = *reinterpret_cast<const float4*>(&Bs[k][tx * 8]);
            *reinterpret_cast<float4*>(b + 4) = *reinterpret_cast<const float4*>(&Bs[k][tx * 8 + 4]);
#pragma unroll
            for (int i = 0; i < 8; i++)
#pragma unroll
                for (int j = 0; j < 8; j++)
                    acc[i][j] = fmaf(a[i], b[j], acc[i][j]);
        }
        __syncthreads();
    }

    // Epilogue: add bias, write out
#pragma unroll
    for (int i = 0; i < 8; i++) {
        int row = by * BM + ty * 8 + i;
#pragma unroll
        for (int j = 0; j < 8; j += 4) {
            int col = bx * BN + tx * 8 + j;
            float4 bi = *reinterpret_cast<const float4*>(bias + col);
            float4 o;
            o.x = acc[i][j + 0] + bi.x;
            o.y = acc[i][j + 1] + bi.y;
            o.z = acc[i][j + 2] + bi.z;
            o.w = acc[i][j + 3] + bi.w;
            *reinterpret_cast<float4*>(out + (size_t)row * NDIM + col) = o;
        }
    }
}

// ---------------------------------------------------------------------------
// Launch: fold then GEMM on the same (default) stream — graph-capturable,
// no allocations, deterministic.
// ---------------------------------------------------------------------------
extern "C" void kernel_launch(void* const* d_in, const int* in_sizes, int n_in,
                              void* d_out, int out_size) {
    const float* x      = (const float*)d_in[0];  // [B,S,M] = [4,2048,1024]
    const float* binary = (const float*)d_in[1];  // [K,M,N] = [8,1024,1024]
    const float* scale  = (const float*)d_in[2];  // [K,1,N]
    const float* bias   = (const float*)d_in[3];  // [N]
    float* out = (float*)d_out;                   // [B,S,N] -> [8192,1024]

    // Stage 1: fold binary*scale -> W
    {
        int total4 = (MDIM * NDIM) / 4;
        fold_kernel<<<total4 / 256, 256>>>(binary, scale);
    }
    // Stage 2: out = x @ W + bias
    {
        dim3 grid(NDIM / BN, TROWS / BM);
        sgemm_bias_kernel<<<grid, 256>>>(x, bias, out);
    }
}

// round 3
// speedup vs baseline: 2.2644x; 2.2644x over previous
#include <cuda_runtime.h>
#include <cuda_bf16.h>
#include <cstdint>

// Problem constants (fixed by the dataset)
#define KBITS 8
#define MDIM  1024   // in_features  (GEMM K)
#define NDIM  1024   // out_features
#define TROWS 8192   // B*S

// ---------------------------------------------------------------------------
// Device scratch (static __device__ arrays — allocation-free)
// ---------------------------------------------------------------------------
__device__ __nv_bfloat16 g_xh[TROWS * MDIM];   // 16 MB bf16(x)
__device__ __nv_bfloat16 g_xl[TROWS * MDIM];   // 16 MB bf16(x - hi)
__device__ __nv_bfloat16 g_wh[NDIM * MDIM];    //  2 MB W^T hi  [n][m] (k-contig)
__device__ __nv_bfloat16 g_wl[NDIM * MDIM];    //  2 MB W^T lo

__device__ __forceinline__ uint32_t smem_u32(const void* p) {
    uint32_t a;
    asm("{ .reg .u64 t; cvta.to.shared.u64 t, %1; cvt.u32.u64 %0, t; }" : "=r"(a) : "l"(p));
    return a;
}

// ---------------------------------------------------------------------------
// Prep 1: split x into bf16 hi/lo
// ---------------------------------------------------------------------------
__global__ __launch_bounds__(256)
void split_x_kernel(const float* __restrict__ x) {
    int idx = (blockIdx.x * 256 + threadIdx.x) * 4;
    float4 v = *reinterpret_cast<const float4*>(x + idx);
    __nv_bfloat16 h[4], l[4];
    float f[4] = {v.x, v.y, v.z, v.w};
#pragma unroll
    for (int i = 0; i < 4; i++) {
        h[i] = __float2bfloat16(f[i]);
        l[i] = __float2bfloat16(f[i] - __bfloat162float(h[i]));
    }
    *reinterpret_cast<uint2*>(g_xh + idx) = *reinterpret_cast<uint2*>(h);
    *reinterpret_cast<uint2*>(g_xl + idx) = *reinterpret_cast<uint2*>(l);
}

// ---------------------------------------------------------------------------
// Prep 2: fold binary*scale into W, transpose to [n][m], split to bf16 hi/lo.
// ---------------------------------------------------------------------------
__global__ __launch_bounds__(256)
void fold_kernel(const float* __restrict__ binary,
                 const float* __restrict__ scale) {
    __shared__ float tile[32][33];
    const int n0 = blockIdx.x * 32;
    const int m0 = blockIdx.y * 32;
    const int tx = threadIdx.x;   // 0..31
    const int ty = threadIdx.y;   // 0..7

    float s[KBITS];
#pragma unroll
    for (int k = 0; k < KBITS; k++) s[k] = scale[k * NDIM + n0 + tx];

#pragma unroll
    for (int r = 0; r < 4; r++) {
        int m = m0 + ty + r * 8;
        float acc = 0.f;
#pragma unroll
        for (int k = 0; k < KBITS; k++)
            acc += binary[(size_t)k * MDIM * NDIM + (size_t)m * NDIM + n0 + tx] * s[k];
        tile[ty + r * 8][tx] = acc;
    }
    __syncthreads();
#pragma unroll
    for (int r = 0; r < 4; r++) {
        int n = n0 + ty + r * 8;
        int m = m0 + tx;
        float w = tile[tx][ty + r * 8];
        __nv_bfloat16 h = __float2bfloat16(w);
        __nv_bfloat16 l = __float2bfloat16(w - __bfloat162float(h));
        g_wh[(size_t)n * MDIM + m] = h;
        g_wl[(size_t)n * MDIM + m] = l;
    }
}

// ---------------------------------------------------------------------------
// Main GEMM via mma.sync bf16 (HMMA): out = xh@Wh + xl@Wh + xh@Wl + bias
// CTA tile 128x128, 8 warps of 64x32, KC=32, double-buffered cp.async.
// ---------------------------------------------------------------------------
#define BM 128
#define BN 128
#define KC 32
#define TILE_B   (128 * 64)            // one operand tile: 128 rows x 64 bytes
#define STAGE_B  (4 * TILE_B)          // Ah, Al, Bh, Bl = 32 KB
#define SMEM_DYN (2 * STAGE_B + 128)   // two stages + align slack

__device__ __forceinline__ void cp16(uint32_t saddr, const void* gaddr) {
    asm volatile("cp.async.cg.shared.global [%0], [%1], 16;"
                 :: "r"(saddr), "l"(gaddr) : "memory");
}
__device__ __forceinline__ void ldsm_x4(uint32_t* r, uint32_t addr) {
    asm volatile("ldmatrix.sync.aligned.m8n8.x4.shared.b16 {%0,%1,%2,%3}, [%4];"
                 : "=r"(r[0]), "=r"(r[1]), "=r"(r[2]), "=r"(r[3]) : "r"(addr));
}
__device__ __forceinline__ void mma_bf16(float* d, const uint32_t* a, const uint32_t* b) {
    asm volatile("mma.sync.aligned.m16n8k16.row.col.f32.bf16.bf16.f32 "
                 "{%0,%1,%2,%3}, {%4,%5,%6,%7}, {%8,%9}, {%0,%1,%2,%3};"
                 : "+f"(d[0]), "+f"(d[1]), "+f"(d[2]), "+f"(d[3])
                 : "r"(a[0]), "r"(a[1]), "r"(a[2]), "r"(a[3]), "r"(b[0]), "r"(b[1]));
}

__global__ __launch_bounds__(256)
void gemm_kernel(const float* __restrict__ bias, float* __restrict__ out) {
    extern __shared__ char smem_raw[];
    uint32_t sbase = (smem_u32(smem_raw) + 127u) & ~127u;

    const int tid = threadIdx.x;
    const int wid = tid >> 5, lid = tid & 31;
    const int warp_m = wid & 1;    // 2 warps along M (64 each)
    const int warp_n = wid >> 1;   // 4 warps along N (32 each)
    const int bx = blockIdx.x, by = blockIdx.y;

    const char* gAh = (const char*)(g_xh + (size_t)by * BM * MDIM);
    const char* gAl = (const char*)(g_xl + (size_t)by * BM * MDIM);
    const char* gBh = (const char*)(g_wh + (size_t)bx * BN * MDIM);
    const char* gBl = (const char*)(g_wl + (size_t)bx * BN * MDIM);

    // cp.async thread mapping: tile = 512 x 16B chunks; 2 per thread per tile.
    // Swizzle: physical chunk = c ^ ((row>>1)&3)  -> conflict-free ldmatrix.
    int id0 = tid, id1 = tid + 256;
    int row0g = id0 >> 2, cc0 = id0 & 3;
    int row1g = id1 >> 2, cc1 = id1 & 3;
    uint32_t d0 = row0g * 64 + ((cc0 ^ ((row0g >> 1) & 3)) << 4);
    uint32_t d1 = row1g * 64 + ((cc1 ^ ((row1g >> 1) & 3)) << 4);

    // ldmatrix lane offsets (relative to operand tile base), k-step 0.
    // A fragment f: rows warp_m*64 + f*16 + (lid&15), chunk = (lid>>4)
    uint32_t aoff[4];
#pragma unroll
    for (int f = 0; f < 4; f++) {
        int row = warp_m * 64 + f * 16 + (lid & 15);
        int hl = lid >> 4;
        aoff[f] = row * 64 + ((hl ^ ((row >> 1) & 3)) << 4);
    }
    // B fragment u (n16 block): rows warp_n*32 + u*16 + ((lid>>4)&1)*8 + (lid&7),
    // chunk = (lid>>3)&1
    uint32_t boff[2];
#pragma unroll
    for (int u = 0; u < 2; u++) {
        int nrow = warp_n * 32 + u * 16 + ((lid >> 4) & 1) * 8 + (lid & 7);
        int ch = (lid >> 3) & 1;
        boff[u] = nrow * 64 + ((ch ^ ((nrow >> 1) & 3)) << 4);
    }

    float acc[4][4][4];
#pragma unroll
    for (int i = 0; i < 4; i++)
#pragma unroll
        for (int j = 0; j < 4; j++)
#pragma unroll
            for (int q = 0; q < 4; q++) acc[i][j][q] = 0.f;

    // ---- pipeline ----
    const int NCH = MDIM / KC;  // 32
    auto issue = [&](int stage, int k0) {
        uint32_t sb = sbase + stage * STAGE_B;
        size_t s0 = (size_t)row0g * 2048 + k0 * 2 + cc0 * 16;
        size_t s1 = (size_t)row1g * 2048 + k0 * 2 + cc1 * 16;
        cp16(sb + 0 * TILE_B + d0, gAh + s0);
        cp16(sb + 0 * TILE_B + d1, gAh + s1);
        cp16(sb + 1 * TILE_B + d0, gAl + s0);
        cp16(sb + 1 * TILE_B + d1, gAl + s1);
        cp16(sb + 2 * TILE_B + d0, gBh + s0);
        cp16(sb + 2 * TILE_B + d1, gBh + s1);
        cp16(sb + 3 * TILE_B + d0, gBl + s0);
        cp16(sb + 3 * TILE_B + d1, gBl + s1);
        asm volatile("cp.async.commit_group;" ::: "memory");
    };

    issue(0, 0);
    for (int c = 0; c < NCH; c++) {
        if (c + 1 < NCH) {
            issue((c + 1) & 1, (c + 1) * KC);
            asm volatile("cp.async.wait_group 1;" ::: "memory");
        } else {
            asm volatile("cp.async.wait_group 0;" ::: "memory");
        }
        __syncthreads();

        uint32_t sb = sbase + (c & 1) * STAGE_B;
        uint32_t sAh = sb, sAl = sb + TILE_B, sBh = sb + 2 * TILE_B, sBl = sb + 3 * TILE_B;
#pragma unroll
        for (int ks = 0; ks < 2; ks++) {
            uint32_t kx = ks << 5;  // XOR 0x20 advances chunk pair
            uint32_t ah[4][4], al[4][4], bh[2][4], bl[2][4];
#pragma unroll
            for (int f = 0; f < 4; f++) ldsm_x4(ah[f], sAh + (aoff[f] ^ kx));
#pragma unroll
            for (int f = 0; f < 4; f++) ldsm_x4(al[f], sAl + (aoff[f] ^ kx));
#pragma unroll
            for (int u = 0; u < 2; u++) ldsm_x4(bh[u], sBh + (boff[u] ^ kx));
#pragma unroll
            for (int u = 0; u < 2; u++) ldsm_x4(bl[u], sBl + (boff[u] ^ kx));
#pragma unroll
            for (int i = 0; i < 4; i++) {
#pragma unroll
                for (int j = 0; j < 4; j++) {
                    const uint32_t* bph = &bh[j >> 1][(j & 1) * 2];
                    const uint32_t* bpl = &bl[j >> 1][(j & 1) * 2];
                    mma_bf16(acc[i][j], ah[i], bph);
                    mma_bf16(acc[i][j], al[i], bph);
                    mma_bf16(acc[i][j], ah[i], bpl);
                }
            }
        }
        __syncthreads();
    }

    // ---- epilogue: bias + store ----
    const int row0 = by * BM + warp_m * 64;
    const int col0 = bx * BN + warp_n * 32;
    const int lrow = lid >> 2;
    const int lcol = (lid & 3) * 2;
#pragma unroll
    for (int j = 0; j < 4; j++) {
        int c0 = col0 + j * 8 + lcol;
        float2 bv = *reinterpret_cast<const float2*>(bias + c0);
#pragma unroll
        for (int i = 0; i < 4; i++) {
            int r = row0 + i * 16 + lrow;
            float2 o0 = {acc[i][j][0] + bv.x, acc[i][j][1] + bv.y};
            float2 o1 = {acc[i][j][2] + bv.x, acc[i][j][3] + bv.y};
            *reinterpret_cast<float2*>(out + (size_t)r * NDIM + c0) = o0;
            *reinterpret_cast<float2*>(out + (size_t)(r + 8) * NDIM + c0) = o1;
        }
    }
}

// ---------------------------------------------------------------------------
// Launch
// ---------------------------------------------------------------------------
extern "C" void kernel_launch(void* const* d_in, const int* in_sizes, int n_in,
                              void* d_out, int out_size) {
    const float* x      = (const float*)d_in[0];  // [4,2048,1024]
    const float* binary = (const float*)d_in[1];  // [8,1024,1024]
    const float* scale  = (const float*)d_in[2];  // [8,1,1024]
    const float* bias   = (const float*)d_in[3];  // [1024]
    float* out = (float*)d_out;

    split_x_kernel<<<(TROWS * MDIM) / 4 / 256, 256>>>(x);
    fold_kernel<<<dim3(NDIM / 32, MDIM / 32), dim3(32, 8)>>>(binary, scale);

    cudaFuncSetAttribute(gemm_kernel, cudaFuncAttributeMaxDynamicSharedMemorySize, SMEM_DYN);
    gemm_kernel<<<dim3(NDIM / BN, TROWS / BM), 256, SMEM_DYN>>>(bias, out);
}

// round 4
// speedup vs baseline: 3.5686x; 1.5760x over previous
#include <cuda_runtime.h>
#include <cuda_fp16.h>
#include <cstdint>

// Problem constants (fixed by the dataset)
#define KBITS 8
#define MDIM  1024   // in_features  (GEMM K)
#define NDIM  1024   // out_features
#define TROWS 8192   // B*S

// ---------------------------------------------------------------------------
// Device scratch
// ---------------------------------------------------------------------------
__device__ __half g_xh[TROWS * MDIM];   // 16 MB  fp16(x)
__device__ __half g_wh[NDIM * MDIM];    //  2 MB  W^T hi  [n][m] (k-contig)
__device__ __half g_wl[NDIM * MDIM];    //  2 MB  W^T lo  (W - Wh residual)

__device__ __forceinline__ uint32_t smem_u32(const void* p) {
    uint32_t a;
    asm("{ .reg .u64 t; cvta.to.shared.u64 t, %1; cvt.u32.u64 %0, t; }" : "=r"(a) : "l"(p));
    return a;
}

// ---------------------------------------------------------------------------
// Prep 1: x -> fp16
// ---------------------------------------------------------------------------
__global__ __launch_bounds__(256)
void split_x_kernel(const float* __restrict__ x) {
    int idx = (blockIdx.x * 256 + threadIdx.x) * 4;
    float4 v = *reinterpret_cast<const float4*>(x + idx);
    __half h[4];
    h[0] = __float2half_rn(v.x);
    h[1] = __float2half_rn(v.y);
    h[2] = __float2half_rn(v.z);
    h[3] = __float2half_rn(v.w);
    *reinterpret_cast<uint2*>(g_xh + idx) = *reinterpret_cast<uint2*>(h);
}

// ---------------------------------------------------------------------------
// Prep 2: fold binary*scale -> W, transpose to [n][m], split to fp16 hi/lo.
// ---------------------------------------------------------------------------
__global__ __launch_bounds__(256)
void fold_kernel(const float* __restrict__ binary,
                 const float* __restrict__ scale) {
    __shared__ float tile[32][33];
    const int n0 = blockIdx.x * 32;
    const int m0 = blockIdx.y * 32;
    const int tx = threadIdx.x;   // 0..31
    const int ty = threadIdx.y;   // 0..7

    float s[KBITS];
#pragma unroll
    for (int k = 0; k < KBITS; k++) s[k] = scale[k * NDIM + n0 + tx];

#pragma unroll
    for (int r = 0; r < 4; r++) {
        int m = m0 + ty + r * 8;
        float acc = 0.f;
#pragma unroll
        for (int k = 0; k < KBITS; k++)
            acc += binary[(size_t)k * MDIM * NDIM + (size_t)m * NDIM + n0 + tx] * s[k];
        tile[ty + r * 8][tx] = acc;
    }
    __syncthreads();
#pragma unroll
    for (int r = 0; r < 4; r++) {
        int n = n0 + ty + r * 8;
        int m = m0 + tx;
        float w = tile[tx][ty + r * 8];
        __half h = __float2half_rn(w);
        __half l = __float2half_rn(w - __half2float(h));
        g_wh[(size_t)n * MDIM + m] = h;
        g_wl[(size_t)n * MDIM + m] = l;
    }
}

// ---------------------------------------------------------------------------
// GEMM: out = xh @ (Wh + Wl) + bias   via mma.sync fp16 (fp32 accum)
// CTA tile 128x128, 8 warps of 64x32, KC=32, 3-stage cp.async pipeline.
// ---------------------------------------------------------------------------
#define BM 128
#define BN 128
#define KC 32
#define STAGES 3
#define TILE_B   (128 * 64)            // one operand tile: 128 rows x 64 bytes
#define STAGE_B  (3 * TILE_B)          // A, Bh, Bl = 24 KB
#define SMEM_DYN (STAGES * STAGE_B + 128)

__device__ __forceinline__ void cp16(uint32_t saddr, const void* gaddr) {
    asm volatile("cp.async.cg.shared.global [%0], [%1], 16;"
                 :: "r"(saddr), "l"(gaddr) : "memory");
}
__device__ __forceinline__ void ldsm_x4(uint32_t* r, uint32_t addr) {
    asm volatile("ldmatrix.sync.aligned.m8n8.x4.shared.b16 {%0,%1,%2,%3}, [%4];"
                 : "=r"(r[0]), "=r"(r[1]), "=r"(r[2]), "=r"(r[3]) : "r"(addr));
}
__device__ __forceinline__ void mma_f16(float* d, const uint32_t* a, const uint32_t* b) {
    asm volatile("mma.sync.aligned.m16n8k16.row.col.f32.f16.f16.f32 "
                 "{%0,%1,%2,%3}, {%4,%5,%6,%7}, {%8,%9}, {%0,%1,%2,%3};"
                 : "+f"(d[0]), "+f"(d[1]), "+f"(d[2]), "+f"(d[3])
                 : "r"(a[0]), "r"(a[1]), "r"(a[2]), "r"(a[3]), "r"(b[0]), "r"(b[1]));
}

__global__ __launch_bounds__(256, 2)
void gemm_kernel(const float* __restrict__ bias, float* __restrict__ out) {
    extern __shared__ char smem_raw[];
    const uint32_t sbase = (smem_u32(smem_raw) + 127u) & ~127u;

    const int tid = threadIdx.x;
    const int wid = tid >> 5, lid = tid & 31;
    const int warp_m = wid & 1;    // 2 warps along M (64 each)
    const int warp_n = wid >> 1;   // 4 warps along N (32 each)
    const int bx = blockIdx.x, by = blockIdx.y;

    const char* gA  = (const char*)(g_xh + (size_t)by * BM * MDIM);
    const char* gBh = (const char*)(g_wh + (size_t)bx * BN * MDIM);
    const char* gBl = (const char*)(g_wl + (size_t)bx * BN * MDIM);

    // cp.async mapping: tile = 512 x 16B chunks; 2 per thread per tile.
    // Swizzle: physical chunk = c ^ ((row>>1)&3).
    const int id0 = tid, id1 = tid + 256;
    const int row0g = id0 >> 2, cc0 = id0 & 3;
    const int row1g = id1 >> 2, cc1 = id1 & 3;
    const uint32_t d0 = row0g * 64 + ((cc0 ^ ((row0g >> 1) & 3)) << 4);
    const uint32_t d1 = row1g * 64 + ((cc1 ^ ((row1g >> 1) & 3)) << 4);

    // ldmatrix lane offsets (ks=0); XOR 0x20 advances to ks=1.
    uint32_t aoff[4];
#pragma unroll
    for (int f = 0; f < 4; f++) {
        int row = warp_m * 64 + f * 16 + (lid & 15);
        int hl = lid >> 4;
        aoff[f] = row * 64 + ((hl ^ ((row >> 1) & 3)) << 4);
    }
    uint32_t boff[2];
#pragma unroll
    for (int u = 0; u < 2; u++) {
        int nrow = warp_n * 32 + u * 16 + ((lid >> 4) & 1) * 8 + (lid & 7);
        int ch = (lid >> 3) & 1;
        boff[u] = nrow * 64 + ((ch ^ ((nrow >> 1) & 3)) << 4);
    }

    float acc[4][4][4];
#pragma unroll
    for (int i = 0; i < 4; i++)
#pragma unroll
        for (int j = 0; j < 4; j++)
#pragma unroll
            for (int q = 0; q < 4; q++) acc[i][j][q] = 0.f;

    const int NCH = MDIM / KC;  // 32
    auto issue = [&](int stage, int k0) {
        uint32_t sb = sbase + stage * STAGE_B;
        size_t s0 = (size_t)row0g * 2048 + k0 * 2 + cc0 * 16;
        size_t s1 = (size_t)row1g * 2048 + k0 * 2 + cc1 * 16;
        cp16(sb + 0 * TILE_B + d0, gA + s0);
        cp16(sb + 0 * TILE_B + d1, gA + s1);
        cp16(sb + 1 * TILE_B + d0, gBh + s0);
        cp16(sb + 1 * TILE_B + d1, gBh + s1);
        cp16(sb + 2 * TILE_B + d0, gBl + s0);
        cp16(sb + 2 * TILE_B + d1, gBl + s1);
        asm volatile("cp.async.commit_group;" ::: "memory");
    };

    issue(0, 0);
    issue(1, KC);

    for (int c = 0; c < NCH; c++) {
        asm volatile("cp.async.wait_group 1;" ::: "memory");
        __syncthreads();
        if (c + 2 < NCH) issue((c + 2) % STAGES, (c + 2) * KC);

        const uint32_t sb = sbase + (c % STAGES) * STAGE_B;
        const uint32_t sA = sb, sBh = sb + TILE_B, sBl = sb + 2 * TILE_B;
#pragma unroll
        for (int ks = 0; ks < 2; ks++) {
            const uint32_t kx = ks << 5;
            uint32_t ah[4][4], bh[2][4], bl[2][4];
#pragma unroll
            for (int f = 0; f < 4; f++) ldsm_x4(ah[f], sA + (aoff[f] ^ kx));
#pragma unroll
            for (int u = 0; u < 2; u++) ldsm_x4(bh[u], sBh + (boff[u] ^ kx));
#pragma unroll
            for (int u = 0; u < 2; u++) ldsm_x4(bl[u], sBl + (boff[u] ^ kx));
#pragma unroll
            for (int i = 0; i < 4; i++) {
#pragma unroll
                for (int j = 0; j < 4; j++) {
                    mma_f16(acc[i][j], ah[i], &bh[j >> 1][(j & 1) * 2]);
                    mma_f16(acc[i][j], ah[i], &bl[j >> 1][(j & 1) * 2]);
                }
            }
        }
    }

    // ---- epilogue: bias + store ----
    const int row0 = by * BM + warp_m * 64;
    const int col0 = bx * BN + warp_n * 32;
    const int lrow = lid >> 2;
    const int lcol = (lid & 3) * 2;
#pragma unroll
    for (int j = 0; j < 4; j++) {
        int c0 = col0 + j * 8 + lcol;
        float2 bv = *reinterpret_cast<const float2*>(bias + c0);
#pragma unroll
        for (int i = 0; i < 4; i++) {
            int r = row0 + i * 16 + lrow;
            float2 o0 = {acc[i][j][0] + bv.x, acc[i][j][1] + bv.y};
            float2 o1 = {acc[i][j][2] + bv.x, acc[i][j][3] + bv.y};
            *reinterpret_cast<float2*>(out + (size_t)r * NDIM + c0) = o0;
            *reinterpret_cast<float2*>(out + (size_t)(r + 8) * NDIM + c0) = o1;
        }
    }
}

// ---------------------------------------------------------------------------
// Launch
// ---------------------------------------------------------------------------
extern "C" void kernel_launch(void* const* d_in, const int* in_sizes, int n_in,
                              void* d_out, int out_size) {
    const float* x      = (const float*)d_in[0];  // [4,2048,1024]
    const float* binary = (const float*)d_in[1];  // [8,1024,1024]
    const float* scale  = (const float*)d_in[2];  // [8,1,1024]
    const float* bias   = (const float*)d_in[3];  // [1024]
    float* out = (float*)d_out;

    split_x_kernel<<<(TROWS * MDIM) / 4 / 256, 256>>>(x);
    fold_kernel<<<dim3(NDIM / 32, MDIM / 32), dim3(32, 8)>>>(binary, scale);

    cudaFuncSetAttribute(gemm_kernel, cudaFuncAttributeMaxDynamicSharedMemorySize, SMEM_DYN);
    gemm_kernel<<<dim3(NDIM / BN, TROWS / BM), 256, SMEM_DYN>>>(bias, out);
}

// round 5
// speedup vs baseline: 5.7576x; 1.6134x over previous
#include <cuda_runtime.h>
#include <cuda_fp16.h>
#include <cstdint>

// Problem constants (fixed by the dataset)
#define KBITS 8
#define MDIM  1024   // in_features  (GEMM K)
#define NDIM  1024   // out_features
#define TROWS 8192   // B*S

// ---------------------------------------------------------------------------
// Device scratch
// ---------------------------------------------------------------------------
__device__ __half g_xh[TROWS * MDIM];   // 16 MB  fp16(x)
__device__ __half g_w[NDIM * MDIM];     //  2 MB  W^T fp16 [n][m] (k-contig)

__device__ __forceinline__ uint32_t smem_u32(const void* p) {
    uint32_t a;
    asm("{ .reg .u64 t; cvta.to.shared.u64 t, %1; cvt.u32.u64 %0, t; }" : "=r"(a) : "l"(p));
    return a;
}

// ---------------------------------------------------------------------------
// Prep 1: x -> fp16 (8 floats per thread)
// ---------------------------------------------------------------------------
__global__ __launch_bounds__(256)
void split_x_kernel(const float* __restrict__ x) {
    int idx = (blockIdx.x * 256 + threadIdx.x) * 8;
    float4 v0 = *reinterpret_cast<const float4*>(x + idx);
    float4 v1 = *reinterpret_cast<const float4*>(x + idx + 4);
    __half h[8];
    h[0] = __float2half_rn(v0.x); h[1] = __float2half_rn(v0.y);
    h[2] = __float2half_rn(v0.z); h[3] = __float2half_rn(v0.w);
    h[4] = __float2half_rn(v1.x); h[5] = __float2half_rn(v1.y);
    h[6] = __float2half_rn(v1.z); h[7] = __float2half_rn(v1.w);
    *reinterpret_cast<uint4*>(g_xh + idx) = *reinterpret_cast<uint4*>(h);
}

// ---------------------------------------------------------------------------
// Prep 2: fold binary*scale -> W, transpose to [n][m], cast fp16.
// ---------------------------------------------------------------------------
__global__ __launch_bounds__(256)
void fold_kernel(const float* __restrict__ binary,
                 const float* __restrict__ scale) {
    __shared__ float tile[32][33];
    const int n0 = blockIdx.x * 32;
    const int m0 = blockIdx.y * 32;
    const int tx = threadIdx.x;   // 0..31
    const int ty = threadIdx.y;   // 0..7

    float s[KBITS];
#pragma unroll
    for (int k = 0; k < KBITS; k++) s[k] = scale[k * NDIM + n0 + tx];

#pragma unroll
    for (int r = 0; r < 4; r++) {
        int m = m0 + ty + r * 8;
        float acc = 0.f;
#pragma unroll
        for (int k = 0; k < KBITS; k++)
            acc += binary[(size_t)k * MDIM * NDIM + (size_t)m * NDIM + n0 + tx] * s[k];
        tile[ty + r * 8][tx] = acc;
    }
    __syncthreads();
#pragma unroll
    for (int r = 0; r < 4; r++) {
        int n = n0 + ty + r * 8;
        int m = m0 + tx;
        g_w[(size_t)n * MDIM + m] = __float2half_rn(tile[tx][ty + r * 8]);
    }
}

// ---------------------------------------------------------------------------
// GEMM: out = xh @ W + bias  via mma.sync fp16 (fp32 accum)
// CTA 128x128, 8 warps (64x32 each), KC=64, 3-stage cp.async pipeline.
// SMEM rows are 128 B (64 fp16); swizzle: chunk ^= (row & 7).
// ---------------------------------------------------------------------------
#define BM 128
#define BN 128
#define KC 64
#define STAGES 3
#define TILE_B   (128 * 128)           // one operand tile: 128 rows x 128 bytes
#define STAGE_B  (2 * TILE_B)          // A + B = 32 KB
#define SMEM_DYN (STAGES * STAGE_B + 128)

__device__ __forceinline__ void cp16(uint32_t saddr, const void* gaddr) {
    asm volatile("cp.async.cg.shared.global [%0], [%1], 16;"
                 :: "r"(saddr), "l"(gaddr) : "memory");
}
__device__ __forceinline__ void ldsm_x4(uint32_t* r, uint32_t addr) {
    asm volatile("ldmatrix.sync.aligned.m8n8.x4.shared.b16 {%0,%1,%2,%3}, [%4];"
                 : "=r"(r[0]), "=r"(r[1]), "=r"(r[2]), "=r"(r[3]) : "r"(addr));
}
__device__ __forceinline__ void mma_f16(float* d, const uint32_t* a, const uint32_t* b) {
    asm volatile("mma.sync.aligned.m16n8k16.row.col.f32.f16.f16.f32 "
                 "{%0,%1,%2,%3}, {%4,%5,%6,%7}, {%8,%9}, {%0,%1,%2,%3};"
                 : "+f"(d[0]), "+f"(d[1]), "+f"(d[2]), "+f"(d[3])
                 : "r"(a[0]), "r"(a[1]), "r"(a[2]), "r"(a[3]), "r"(b[0]), "r"(b[1]));
}

__global__ __launch_bounds__(256, 2)
void gemm_kernel(const float* __restrict__ bias, float* __restrict__ out) {
    extern __shared__ char smem_raw[];
    const uint32_t sbase = (smem_u32(smem_raw) + 127u) & ~127u;

    const int tid = threadIdx.x;
    const int wid = tid >> 5, lid = tid & 31;
    const int warp_m = wid & 1;    // 2 warps along M (64 each)
    const int warp_n = wid >> 1;   // 4 warps along N (32 each)
    const int bx = blockIdx.x, by = blockIdx.y;

    const char* gA = (const char*)(g_xh + (size_t)by * BM * MDIM);
    const char* gB = (const char*)(g_w  + (size_t)bx * BN * MDIM);

    // cp.async mapping: tile = 128 rows x 8 chunks (16B); 4 chunks/thread/tile.
    int ld_row[4], ld_c[4];
    uint32_t ld_dst[4];
#pragma unroll
    for (int i = 0; i < 4; i++) {
        int id = tid + i * 256;
        ld_row[i] = id >> 3;
        ld_c[i] = id & 7;
        ld_dst[i] = ld_row[i] * 128 + ((ld_c[i] ^ (ld_row[i] & 7)) << 4);
    }

    // ldmatrix row bases (chunk varies per ks)
    int arow[4];
#pragma unroll
    for (int f = 0; f < 4; f++) arow[f] = warp_m * 64 + f * 16 + (lid & 15);
    const int a_hl = lid >> 4;                 // 0/1 : k8-half
    int brow[2];
#pragma unroll
    for (int u = 0; u < 2; u++)
        brow[u] = warp_n * 32 + u * 16 + ((lid >> 4) & 1) * 8 + (lid & 7);
    const int b_ch = (lid >> 3) & 1;           // 0/1 : k8-half

    float acc[4][4][4];
#pragma unroll
    for (int i = 0; i < 4; i++)
#pragma unroll
        for (int j = 0; j < 4; j++)
#pragma unroll
            for (int q = 0; q < 4; q++) acc[i][j][q] = 0.f;

    const int NCH = MDIM / KC;  // 16
    auto issue = [&](int stage, int k0) {
        uint32_t sb = sbase + stage * STAGE_B;
#pragma unroll
        for (int i = 0; i < 4; i++) {
            size_t src = (size_t)ld_row[i] * (MDIM * 2) + k0 * 2 + ld_c[i] * 16;
            cp16(sb + ld_dst[i], gA + src);
            cp16(sb + TILE_B + ld_dst[i], gB + src);
        }
        asm volatile("cp.async.commit_group;" ::: "memory");
    };

    issue(0, 0);
    issue(1, KC);

    for (int c = 0; c < NCH; c++) {
        asm volatile("cp.async.wait_group 1;" ::: "memory");
        __syncthreads();
        if (c + 2 < NCH) issue((c + 2) % STAGES, (c + 2) * KC);

        const uint32_t sA = sbase + (c % STAGES) * STAGE_B;
        const uint32_t sB = sA + TILE_B;
#pragma unroll
        for (int ks = 0; ks < 4; ks++) {
            uint32_t a[4][4], b[2][4];
#pragma unroll
            for (int f = 0; f < 4; f++)
                ldsm_x4(a[f], sA + arow[f] * 128 +
                              (((ks * 2 + a_hl) ^ (arow[f] & 7)) << 4));
#pragma unroll
            for (int u = 0; u < 2; u++)
                ldsm_x4(b[u], sB + brow[u] * 128 +
                              (((ks * 2 + b_ch) ^ (brow[u] & 7)) << 4));
#pragma unroll
            for (int i = 0; i < 4; i++)
#pragma unroll
                for (int j = 0; j < 4; j++)
                    mma_f16(acc[i][j], a[i], &b[j >> 1][(j & 1) * 2]);
        }
    }

    // ---- epilogue: bias + store ----
    const int row0 = by * BM + warp_m * 64;
    const int col0 = bx * BN + warp_n * 32;
    const int lrow = lid >> 2;
    const int lcol = (lid & 3) * 2;
#pragma unroll
    for (int j = 0; j < 4; j++) {
        int c0 = col0 + j * 8 + lcol;
        float2 bv = *reinterpret_cast<const float2*>(bias + c0);
#pragma unroll
        for (int i = 0; i < 4; i++) {
            int r = row0 + i * 16 + lrow;
            float2 o0 = {acc[i][j][0] + bv.x, acc[i][j][1] + bv.y};
            float2 o1 = {acc[i][j][2] + bv.x, acc[i][j][3] + bv.y};
            *reinterpret_cast<float2*>(out + (size_t)r * NDIM + c0) = o0;
            *reinterpret_cast<float2*>(out + (size_t)(r + 8) * NDIM + c0) = o1;
        }
    }
}

// ---------------------------------------------------------------------------
// Launch
// ---------------------------------------------------------------------------
extern "C" void kernel_launch(void* const* d_in, const int* in_sizes, int n_in,
                              void* d_out, int out_size) {
    const float* x      = (const float*)d_in[0];  // [4,2048,1024]
    const float* binary = (const float*)d_in[1];  // [8,1024,1024]
    const float* scale  = (const float*)d_in[2];  // [8,1,1024]
    const float* bias   = (const float*)d_in[3];  // [1024]
    float* out = (float*)d_out;

    split_x_kernel<<<(TROWS * MDIM) / 8 / 256, 256>>>(x);
    fold_kernel<<<dim3(NDIM / 32, MDIM / 32), dim3(32, 8)>>>(binary, scale);

    cudaFuncSetAttribute(gemm_kernel, cudaFuncAttributeMaxDynamicSharedMemorySize, SMEM_DYN);
    gemm_kernel<<<dim3(NDIM / BN, TROWS / BM), 256, SMEM_DYN>>>(bias, out);
}